// round 16
// baseline (speedup 1.0000x reference)
#include <cuda_runtime.h>
#include <cuda_bf16.h>
#include <cstdint>

// Problem constants
#define BB 32
#define TT 1024
#define DD 128
#define HH 4
#define DHH 32
#define MROWS (BB*TT)   // 32768

// Scratch (device globals — no allocation allowed)
__device__ __align__(16) uint32_t g_Asp[MROWS * DD];    // attn out pre-split
__device__ __align__(16) uint32_t g_Qsp[MROWS * HH * 32];        // Q split (scaled)
__device__ __align__(16) uint32_t g_Ksp[BB * HH * TT * 32];      // K split rows: 16 hi + 16 lo
__device__ __align__(16) uint32_t g_Vth[BB * HH * 32 * (TT/2)];  // V^T hi: [bh][d][jp]
__device__ __align__(16) uint32_t g_Vtl[BB * HH * 32 * (TT/2)];  // V^T lo

// ---------------------------------------------------------------------------
// helpers
// ---------------------------------------------------------------------------
__device__ __forceinline__ uint32_t smem_u32(const void* p) {
    uint32_t a;
    asm("{ .reg .u64 t; cvta.to.shared.u64 t, %1; cvt.u32.u64 %0, t; }"
        : "=r"(a) : "l"(p));
    return a;
}

__device__ __forceinline__ uint32_t split_pack(float x) {
    __nv_bfloat16 h = __float2bfloat16(x);
    float r = x - __bfloat162float(h);
    __nv_bfloat16 l = __float2bfloat16(r);
    return (uint32_t)__bfloat16_as_ushort(h) | ((uint32_t)__bfloat16_as_ushort(l) << 16);
}

__device__ __forceinline__ uint32_t pack_bf16x2(float x, float y) {
    uint32_t d;
    asm("cvt.rn.bf16x2.f32 %0, %1, %2;" : "=r"(d) : "f"(y), "f"(x));
    return d;
}

__device__ __forceinline__ void pair_split(float x, float y,
                                           uint32_t& hi, uint32_t& lo) {
    hi = pack_bf16x2(x, y);
    float hx = __uint_as_float(hi << 16);
    float hy = __uint_as_float(hi & 0xffff0000u);
    lo = pack_bf16x2(x - hx, y - hy);
}

__device__ __forceinline__ float ex2f(float x) {
    float r;
    asm("ex2.approx.ftz.f32 %0, %1;" : "=f"(r) : "f"(x));
    return r;
}

#define LDSM_X4(r0, r1, r2, r3, addr) \
    asm volatile("ldmatrix.sync.aligned.m8n8.x4.shared.b16 {%0,%1,%2,%3}, [%4];" \
                 : "=r"(r0), "=r"(r1), "=r"(r2), "=r"(r3) : "r"(addr))

#define LDSM_X2(r0, r1, addr) \
    asm volatile("ldmatrix.sync.aligned.m8n8.x2.shared.b16 {%0,%1}, [%2];" \
                 : "=r"(r0), "=r"(r1) : "r"(addr))

#define MMA_16816(c, a, b) \
    asm volatile("mma.sync.aligned.m16n8k16.row.col.f32.bf16.bf16.f32 " \
                 "{%0,%1,%2,%3}, {%4,%5,%6,%7}, {%8,%9}, {%0,%1,%2,%3};" \
                 : "+f"((c)[0]), "+f"((c)[1]), "+f"((c)[2]), "+f"((c)[3]) \
                 : "r"((a)[0]), "r"((a)[1]), "r"((a)[2]), "r"((a)[3]), \
                   "r"((b)[0]), "r"((b)[1]))

#define CP_ASYNC16(dst, src) \
    asm volatile("cp.async.cg.shared.global [%0], [%1], 16;" :: "r"(dst), "l"(src))
#define CP_COMMIT() asm volatile("cp.async.commit_group;" ::: "memory")
#define CP_WAIT(n)  asm volatile("cp.async.wait_group %0;" :: "n"(n) : "memory")

// ---------------------------------------------------------------------------
// QKV HMMA GEMM: reads fp32 x and fp32 W directly, splits in-kernel.
// M-tile 128; fused epilogues: y=0 Q->Qsp, y=1 K->Ksp, y=2 V->Vth/Vtl.
// ---------------------------------------------------------------------------
__global__ __launch_bounds__(256) void gemm_qkv(
    const float* __restrict__ X, const float* __restrict__ W,
    uint32_t* __restrict__ Qsp, uint32_t* __restrict__ Ksp,
    uint32_t* __restrict__ Vth, uint32_t* __restrict__ Vtl) {
    __shared__ uint32_t As_s[128 * 36];
    __shared__ uint32_t Bs_s[128 * 36];

    const int tid = threadIdx.x;
    const int wid = tid >> 5;
    const int lane = tid & 31;
    const int wm = wid >> 2;
    const int wn = wid & 3;
    const int m0 = blockIdx.x * 128;
    const int y = blockIdx.y;
    const int n0 = y * 128;

    const uint32_t sa = smem_u32(As_s);
    const uint32_t sb = smem_u32(Bs_s);

    float acc[4][4][4];
#pragma unroll
    for (int i = 0; i < 4; i++)
#pragma unroll
        for (int j = 0; j < 4; j++)
#pragma unroll
            for (int q = 0; q < 4; q++) acc[i][j][q] = 0.f;

    const int a_row = lane & 15;
    const int a_koff = (lane >> 4) * 4;
    const int b_row = lane & 7;
    const int b_koff = ((lane >> 3) & 1) * 4;

    for (int ch = 0; ch < 4; ch++) {
        const int kc = ch * 32;
        // A chunk: 128 rows x 32 fp32 of x -> split in-kernel
#pragma unroll
        for (int r = 0; r < 4; r++) {
            int idx = tid + r * 256;
            int row = idx >> 3, c4 = idx & 7;
            float4 v = *(const float4*)&X[(size_t)(m0 + row) * 128 + kc + c4 * 4];
            uint32_t* d = &As_s[row * 36 + c4 * 4];
            d[0] = split_pack(v.x); d[1] = split_pack(v.y);
            d[2] = split_pack(v.z); d[3] = split_pack(v.w);
        }
        // B chunk: W[kc+k][n0+n] fp32, transpose+split -> Bs[n][k]
#pragma unroll
        for (int r = 0; r < 16; r++) {
            int idx = tid + r * 256;       // 0..4095
            int k = idx >> 7, n = idx & 127;
            Bs_s[n * 36 + k] = split_pack(W[(size_t)(kc + k) * 384 + n0 + n]);
        }
        __syncthreads();

#pragma unroll
        for (int s = 0; s < 4; s++) {
            uint32_t af[4][4];
#pragma unroll
            for (int tm = 0; tm < 4; tm++) {
                uint32_t addr = sa + (uint32_t)(((wm * 64 + tm * 16 + a_row) * 36 +
                                                 s * 8 + a_koff) * 4);
                LDSM_X4(af[tm][0], af[tm][1], af[tm][2], af[tm][3], addr);
            }
            uint32_t bf[4][2];
#pragma unroll
            for (int tn = 0; tn < 4; tn++) {
                uint32_t addr = sb + (uint32_t)(((wn * 32 + tn * 8 + b_row) * 36 +
                                                 s * 8 + b_koff) * 4);
                LDSM_X2(bf[tn][0], bf[tn][1], addr);
            }
#pragma unroll
            for (int tm = 0; tm < 4; tm++)
#pragma unroll
                for (int tn = 0; tn < 4; tn++)
                    MMA_16816(acc[tm][tn], af[tm], bf[tn]);
        }
        __syncthreads();
    }

    const int er = lane >> 2;
    const int ec = (lane & 3) * 2;
    const float qscale = 0.17677669529663687f * 1.4426950408889634f;

    if (y == 2) {
        float* sv = (float*)As_s;   // stride 34 (even), 128*34*4 = 17.4 KB
        const int b = m0 >> 10;
        const int jb0 = m0 & 1023;
#pragma unroll
        for (int h = 0; h < 4; h++) {
            if (h) __syncthreads();
            if (wn == h) {
#pragma unroll
                for (int tm = 0; tm < 4; tm++) {
#pragma unroll
                    for (int tn = 0; tn < 4; tn++) {
                        int rl = wm * 64 + tm * 16 + er;
                        int cl = tn * 8 + ec;
                        *(float2*)&sv[rl * 34 + cl] =
                            make_float2(acc[tm][tn][0], acc[tm][tn][1]);
                        *(float2*)&sv[(rl + 8) * 34 + cl] =
                            make_float2(acc[tm][tn][2], acc[tm][tn][3]);
                    }
                }
            }
            __syncthreads();
            const int bh = b * 4 + h;
#pragma unroll
            for (int r = 0; r < 8; r++) {
                int idx = tid + r * 256;
                int d = idx >> 6, jp = idx & 63;
                uint32_t hi, lo;
                pair_split(sv[(jp * 2) * 34 + d], sv[(jp * 2 + 1) * 34 + d], hi, lo);
                size_t o = (size_t)(bh * 32 + d) * (TT / 2) + (jb0 >> 1) + jp;
                Vth[o] = hi;
                Vtl[o] = lo;
            }
        }
    } else {
        const float sc = (y == 0) ? qscale : 1.f;
#pragma unroll
        for (int tm = 0; tm < 4; tm++) {
#pragma unroll
            for (int tn = 0; tn < 4; tn++) {
                int row = m0 + wm * 64 + tm * 16 + er;
                int col = wn * 32 + tn * 8 + ec;
                int head = col >> 5;
                int dp = (col & 31) >> 1;
                uint32_t hi0, lo0, hi1, lo1;
                pair_split(acc[tm][tn][0] * sc, acc[tm][tn][1] * sc, hi0, lo0);
                pair_split(acc[tm][tn][2] * sc, acc[tm][tn][3] * sc, hi1, lo1);
                if (y == 0) {
                    uint32_t* d0 = &Qsp[((size_t)row * 4 + head) * 32];
                    uint32_t* d1 = &Qsp[((size_t)(row + 8) * 4 + head) * 32];
                    d0[dp] = hi0; d0[16 + dp] = lo0;
                    d1[dp] = hi1; d1[16 + dp] = lo1;
                } else {
                    int bb = row >> 10;
                    int t0 = row & 1023;
                    uint32_t* d0 = &Ksp[(((size_t)bb * 4 + head) * 1024 + t0) * 32];
                    uint32_t* d1 = d0 + 8 * 32;
                    d0[dp] = hi0; d0[16 + dp] = lo0;
                    d1[dp] = hi1; d1[16 + dp] = lo1;
                }
            }
        }
    }
}

// ---------------------------------------------------------------------------
// Fused output projection: A = pre-split attn output, B = fp32 W_output
// (split in-kernel), residual in acc-init, LayerNorm epilogue.
// ---------------------------------------------------------------------------
__global__ __launch_bounds__(256) void gemm_out_ln(
    const uint32_t* __restrict__ Asp, const float* __restrict__ Wo,
    const float* __restrict__ x, const float* __restrict__ gamma,
    const float* __restrict__ beta, float* __restrict__ out) {
    __shared__ uint32_t As_s[128 * 36];
    __shared__ uint32_t Bs_s[128 * 36];

    const int tid = threadIdx.x;
    const int wid = tid >> 5;
    const int lane = tid & 31;
    const int wm = wid >> 2;
    const int wn = wid & 3;
    const int m0 = blockIdx.x * 128;

    const uint32_t sa = smem_u32(As_s);
    const uint32_t sb = smem_u32(Bs_s);

    const int er = lane >> 2;
    const int ec = (lane & 3) * 2;

    float acc[4][4][4];
#pragma unroll
    for (int tm = 0; tm < 4; tm++) {
#pragma unroll
        for (int tn = 0; tn < 4; tn++) {
            int row = m0 + wm * 64 + tm * 16 + er;
            int col = wn * 32 + tn * 8 + ec;
            float2 x0 = *(const float2*)&x[(size_t)row * 128 + col];
            float2 x1 = *(const float2*)&x[(size_t)(row + 8) * 128 + col];
            acc[tm][tn][0] = x0.x; acc[tm][tn][1] = x0.y;
            acc[tm][tn][2] = x1.x; acc[tm][tn][3] = x1.y;
        }
    }

    const int a_row = lane & 15;
    const int a_koff = (lane >> 4) * 4;
    const int b_row = lane & 7;
    const int b_koff = ((lane >> 3) & 1) * 4;

    for (int ch = 0; ch < 4; ch++) {
        const int kc = ch * 32;
#pragma unroll
        for (int r = 0; r < 4; r++) {
            int idx = tid + r * 256;
            int row = idx >> 3, c4 = idx & 7;
            uint4 v = *(const uint4*)&Asp[(size_t)(m0 + row) * 128 + kc + c4 * 4];
            uint32_t* d = &As_s[row * 36 + c4 * 4];
            d[0] = v.x; d[1] = v.y; d[2] = v.z; d[3] = v.w;
        }
        // B chunk: Wo[kc+k][n] fp32, transpose+split -> Bs[n][k]
#pragma unroll
        for (int r = 0; r < 16; r++) {
            int idx = tid + r * 256;       // 0..4095
            int k = idx >> 7, n = idx & 127;
            Bs_s[n * 36 + k] = split_pack(Wo[(size_t)(kc + k) * 128 + n]);
        }
        __syncthreads();

#pragma unroll
        for (int s = 0; s < 4; s++) {
            uint32_t af[4][4];
#pragma unroll
            for (int tm = 0; tm < 4; tm++) {
                uint32_t addr = sa + (uint32_t)(((wm * 64 + tm * 16 + a_row) * 36 +
                                                 s * 8 + a_koff) * 4);
                LDSM_X4(af[tm][0], af[tm][1], af[tm][2], af[tm][3], addr);
            }
            uint32_t bf[4][2];
#pragma unroll
            for (int tn = 0; tn < 4; tn++) {
                uint32_t addr = sb + (uint32_t)(((wn * 32 + tn * 8 + b_row) * 36 +
                                                 s * 8 + b_koff) * 4);
                LDSM_X2(bf[tn][0], bf[tn][1], addr);
            }
#pragma unroll
            for (int tm = 0; tm < 4; tm++)
#pragma unroll
                for (int tn = 0; tn < 4; tn++)
                    MMA_16816(acc[tm][tn], af[tm], bf[tn]);
        }
        __syncthreads();
    }

    float2* red = (float2*)As_s;
#pragma unroll
    for (int tm = 0; tm < 4; tm++) {
        float s0 = 0.f, q0 = 0.f, s1 = 0.f, q1 = 0.f;
#pragma unroll
        for (int tn = 0; tn < 4; tn++) {
            s0 += acc[tm][tn][0] + acc[tm][tn][1];
            q0 += acc[tm][tn][0] * acc[tm][tn][0] + acc[tm][tn][1] * acc[tm][tn][1];
            s1 += acc[tm][tn][2] + acc[tm][tn][3];
            q1 += acc[tm][tn][2] * acc[tm][tn][2] + acc[tm][tn][3] * acc[tm][tn][3];
        }
#pragma unroll
        for (int off = 1; off < 4; off <<= 1) {
            s0 += __shfl_xor_sync(0xffffffffu, s0, off);
            q0 += __shfl_xor_sync(0xffffffffu, q0, off);
            s1 += __shfl_xor_sync(0xffffffffu, s1, off);
            q1 += __shfl_xor_sync(0xffffffffu, q1, off);
        }
        if ((lane & 3) == 0) {
            int rl = wm * 64 + tm * 16 + er;
            red[wn * 128 + rl] = make_float2(s0, q0);
            red[wn * 128 + rl + 8] = make_float2(s1, q1);
        }
    }
    __syncthreads();

    float2 gm[4], bt[4];
#pragma unroll
    for (int tn = 0; tn < 4; tn++) {
        int col = wn * 32 + tn * 8 + ec;
        gm[tn] = *(const float2*)&gamma[col];
        bt[tn] = *(const float2*)&beta[col];
    }

#pragma unroll
    for (int tm = 0; tm < 4; tm++) {
        int rl = wm * 64 + tm * 16 + er;
        float s0 = 0.f, q0 = 0.f, s1 = 0.f, q1 = 0.f;
#pragma unroll
        for (int w = 0; w < 4; w++) {
            float2 p0 = red[w * 128 + rl];
            float2 p1 = red[w * 128 + rl + 8];
            s0 += p0.x; q0 += p0.y;
            s1 += p1.x; q1 += p1.y;
        }
        float mean0 = s0 * (1.f / 128.f);
        float var0 = q0 * (1.f / 128.f) - mean0 * mean0;
        float rstd0 = rsqrtf(var0 + 1e-9f);
        float mean1 = s1 * (1.f / 128.f);
        float var1 = q1 * (1.f / 128.f) - mean1 * mean1;
        float rstd1 = rsqrtf(var1 + 1e-9f);

        int row = m0 + rl;
#pragma unroll
        for (int tn = 0; tn < 4; tn++) {
            int col = wn * 32 + tn * 8 + ec;
            float2 o0 = make_float2(
                (acc[tm][tn][0] - mean0) * rstd0 * gm[tn].x + bt[tn].x,
                (acc[tm][tn][1] - mean0) * rstd0 * gm[tn].y + bt[tn].y);
            float2 o1 = make_float2(
                (acc[tm][tn][2] - mean1) * rstd1 * gm[tn].x + bt[tn].x,
                (acc[tm][tn][3] - mean1) * rstd1 * gm[tn].y + bt[tn].y);
            *(float2*)&out[(size_t)row * 128 + col] = o0;
            *(float2*)&out[(size_t)(row + 8) * 128 + col] = o1;
        }
    }
}

// ---------------------------------------------------------------------------
// HMMA flash attention, no-max softmax (frozen from R15 113.7us winner).
// ---------------------------------------------------------------------------
__global__ __launch_bounds__(256, 3) void attn_hmma(
    const uint32_t* __restrict__ Qsp, const int* __restrict__ keys_length,
    const uint32_t* __restrict__ Ksp, const uint32_t* __restrict__ Vth,
    const uint32_t* __restrict__ Vtl, uint32_t* __restrict__ outsp) {
    __shared__ __align__(16) uint32_t S[9216];

    const int bid = blockIdx.x;
    const int q0 = (7 - (bid >> 7)) * 128;
    const int bh = bid & 127;
    const int h = bh & 3;
    const int b = bh >> 2;
    const int tid = threadIdx.x;
    const int wid = tid >> 5;
    const int lane = tid & 31;
    const uint32_t sS = smem_u32(S);

    const int L = keys_length[b];
    const int kend = min(q0 + 128, L);
    const int ntiles = (kend + 63) >> 6;

    const uint32_t* kbase = Ksp + (size_t)(bh * TT) * 32;
    const uint32_t* vhbase = Vth + (size_t)(bh * 32) * (TT / 2);
    const uint32_t* vlbase = Vtl + (size_t)(bh * 32) * (TT / 2);

    {
        const uint32_t sk = sS;
        const uint32_t* kt = kbase;
#pragma unroll
        for (int r = 0; r < 2; r++) {
            int idx = tid + r * 256;
            int row = idx >> 3, c4 = idx & 7;
            CP_ASYNC16(sk + (uint32_t)((row * 36 + c4 * 4) * 4), kt + row * 32 + c4 * 4);
        }
        {
            int d = tid >> 3, c4 = tid & 7;
            CP_ASYNC16(sk + (uint32_t)((2304 + d * 36 + c4 * 4) * 4),
                       vhbase + (size_t)d * (TT / 2) + c4 * 4);
            CP_ASYNC16(sk + (uint32_t)((3456 + d * 36 + c4 * 4) * 4),
                       vlbase + (size_t)d * (TT / 2) + c4 * 4);
        }
#pragma unroll
        for (int r = 0; r < 4; r++) {
            int idx = tid + r * 256;
            int row = idx >> 3, c4 = idx & 7;
            CP_ASYNC16(sS + (uint32_t)((4608 + row * 36 + c4 * 4) * 4),
                       Qsp + ((size_t)(b * TT + q0 + row) * 4 + h) * 32 + c4 * 4);
        }
        CP_COMMIT();
    }

    CP_WAIT(0);
    __syncthreads();

    const int a_row = lane & 15;
    const int a_koff = (lane >> 4) * 4;
    uint32_t aH[2][4], aL[2][4];
#pragma unroll
    for (int ks = 0; ks < 2; ks++) {
        uint32_t addr = sS + (uint32_t)((4608 + (wid * 16 + a_row) * 36 + ks * 8 + a_koff) * 4);
        LDSM_X4(aH[ks][0], aH[ks][1], aH[ks][2], aH[ks][3], addr);
        LDSM_X4(aL[ks][0], aL[ks][1], aL[ks][2], aL[ks][3], addr + 64);
    }
    __syncthreads();

    float o[4][4];
#pragma unroll
    for (int nt = 0; nt < 4; nt++)
#pragma unroll
        for (int c = 0; c < 4; c++) o[nt][c] = 0.f;
    float l0 = 0.f, l1 = 0.f;

    const int r0 = q0 + wid * 16 + (lane >> 2);
    const int r1 = r0 + 8;
    const int rmax = q0 + wid * 16 + 15;
    const int b_row = lane & 7;
    const int b_k4 = (lane >> 3) * 4;

    for (int t = 0; t < ntiles; t++) {
        if (t + 1 < ntiles) {
            const uint32_t sk = sS + (uint32_t)(((t + 1) & 1) * 4608 * 4);
            const uint32_t* kt = kbase + (size_t)(t + 1) * 64 * 32;
#pragma unroll
            for (int r = 0; r < 2; r++) {
                int idx = tid + r * 256;
                int row = idx >> 3, c4 = idx & 7;
                CP_ASYNC16(sk + (uint32_t)((row * 36 + c4 * 4) * 4), kt + row * 32 + c4 * 4);
            }
            {
                int d = tid >> 3, c4 = tid & 7;
                CP_ASYNC16(sk + (uint32_t)((2304 + d * 36 + c4 * 4) * 4),
                           vhbase + (size_t)d * (TT / 2) + (t + 1) * 32 + c4 * 4);
                CP_ASYNC16(sk + (uint32_t)((3456 + d * 36 + c4 * 4) * 4),
                           vlbase + (size_t)d * (TT / 2) + (t + 1) * 32 + c4 * 4);
            }
            CP_COMMIT();
            CP_WAIT(1);
        } else {
            CP_WAIT(0);
        }
        __syncthreads();

        const int j0 = t * 64;
        if (j0 <= rmax) {
            const uint32_t skb = sS + (uint32_t)((t & 1) * 4608 * 4);

            float s[8][4];
#pragma unroll
            for (int tt = 0; tt < 8; tt++)
#pragma unroll
                for (int c = 0; c < 4; c++) s[tt][c] = 0.f;

#pragma unroll
            for (int tt = 0; tt < 8; tt++) {
                uint32_t krow = skb + (uint32_t)(((tt * 8 + b_row) * 36 + b_k4) * 4);
                uint32_t bh0[2], bh1[2], bl0[2], bl1[2];
                LDSM_X4(bh0[0], bh0[1], bh1[0], bh1[1], krow);
                LDSM_X4(bl0[0], bl0[1], bl1[0], bl1[1], krow + 64);
                MMA_16816(s[tt], aH[0], bh0);
                MMA_16816(s[tt], aH[1], bh1);
                MMA_16816(s[tt], aL[0], bh0);
                MMA_16816(s[tt], aL[1], bh1);
                MMA_16816(s[tt], aH[0], bl0);
                MMA_16816(s[tt], aH[1], bl1);
            }

            const bool needMask = (j0 + 64 > L) || (j0 + 64 > q0 + wid * 16 + 1);
            if (needMask) {
#pragma unroll
                for (int tt = 0; tt < 8; tt++) {
#pragma unroll
                    for (int c = 0; c < 2; c++) {
                        int j = j0 + tt * 8 + (lane & 3) * 2 + c;
                        if (j > r0 || j >= L) s[tt][c] = -1e30f;
                        if (j > r1 || j >= L) s[tt][2 + c] = -1e30f;
                    }
                }
            }

            // ---- softmax numerator, no max shift ----
#pragma unroll
            for (int tt = 0; tt < 8; tt++) {
                s[tt][0] = ex2f(s[tt][0]);
                s[tt][1] = ex2f(s[tt][1]);
                s[tt][2] = ex2f(s[tt][2]);
                s[tt][3] = ex2f(s[tt][3]);
                l0 += s[tt][0] + s[tt][1];
                l1 += s[tt][2] + s[tt][3];
            }

            // ---- PV: stream P per ks-pair ----
            const uint32_t svhb = skb + 2304 * 4;
            const uint32_t svlb = skb + 3456 * 4;
#pragma unroll
            for (int ksp = 0; ksp < 2; ksp++) {
                uint32_t ph2[2][4], pl2[2][4];
#pragma unroll
                for (int k2 = 0; k2 < 2; k2++) {
                    const int t0 = 4 * ksp + 2 * k2, t1 = t0 + 1;
                    float v[8] = {s[t0][0], s[t0][1], s[t0][2], s[t0][3],
                                  s[t1][0], s[t1][1], s[t1][2], s[t1][3]};
#pragma unroll
                    for (int g = 0; g < 4; g++) {
                        pair_split(v[g * 2], v[g * 2 + 1], ph2[k2][g], pl2[k2][g]);
                    }
                }
#pragma unroll
                for (int nt = 0; nt < 4; nt++) {
                    uint32_t voff = (uint32_t)(((nt * 8 + b_row) * 36 + b_k4) * 4) +
                                    (uint32_t)(ksp * 64);
                    uint32_t bvh[2][2], bvl[2][2];
                    LDSM_X4(bvh[0][0], bvh[0][1], bvh[1][0], bvh[1][1], svhb + voff);
                    LDSM_X4(bvl[0][0], bvl[0][1], bvl[1][0], bvl[1][1], svlb + voff);
#pragma unroll
                    for (int k2 = 0; k2 < 2; k2++) {
                        MMA_16816(o[nt], ph2[k2], bvh[k2]);
                        MMA_16816(o[nt], pl2[k2], bvh[k2]);
                        MMA_16816(o[nt], ph2[k2], bvl[k2]);
                    }
                }
            }
        }
        __syncthreads();
    }

    l0 += __shfl_xor_sync(0xffffffffu, l0, 1);
    l0 += __shfl_xor_sync(0xffffffffu, l0, 2);
    l1 += __shfl_xor_sync(0xffffffffu, l1, 1);
    l1 += __shfl_xor_sync(0xffffffffu, l1, 2);
    const float inv0 = 1.f / l0, inv1 = 1.f / l1;
#pragma unroll
    for (int nt = 0; nt < 4; nt++) {
        int d = h * 32 + nt * 8 + (lane & 3) * 2;
        *(uint2*)&outsp[((size_t)(b * TT + r0)) * DD + d] =
            make_uint2(split_pack(o[nt][0] * inv0), split_pack(o[nt][1] * inv0));
        *(uint2*)&outsp[((size_t)(b * TT + r1)) * DD + d] =
            make_uint2(split_pack(o[nt][2] * inv1), split_pack(o[nt][3] * inv1));
    }
}

// ---------------------------------------------------------------------------
extern "C" void kernel_launch(void* const* d_in, const int* in_sizes, int n_in,
                              void* d_out, int out_size) {
    const float* x           = (const float*)d_in[0];
    const int*   keys_length = (const int*)d_in[1];
    const float* W           = (const float*)d_in[2];
    const float* W_output    = (const float*)d_in[3];
    const float* gamma       = (const float*)d_in[4];
    const float* beta        = (const float*)d_in[5];
    float* out = (float*)d_out;

    uint32_t *asp_p, *qsp_p, *ksp_p, *vth_p, *vtl_p;
    cudaGetSymbolAddress((void**)&asp_p, g_Asp);
    cudaGetSymbolAddress((void**)&qsp_p, g_Qsp);
    cudaGetSymbolAddress((void**)&ksp_p, g_Ksp);
    cudaGetSymbolAddress((void**)&vth_p, g_Vth);
    cudaGetSymbolAddress((void**)&vtl_p, g_Vtl);

    // 1) QKV projection: fp32 x and W split in-kernel; epilogues emit
    //    Qsp/Ksp/Vth/Vtl
    gemm_qkv<<<dim3(MROWS / 128, 3), 256>>>(x, W, qsp_p, ksp_p, vth_p, vtl_p);

    // 2) Flash attention (HMMA, no-max softmax); output pre-split
    attn_hmma<<<1024, 256>>>(qsp_p, keys_length, ksp_p, vth_p, vtl_p, asp_p);

    // 3) Output projection (fp32 W_output split in-kernel) + residual + LN
    gemm_out_ln<<<MROWS / 128, 256>>>(asp_p, W_output, x, gamma, beta, out);
}

// round 17
// speedup vs baseline: 1.0517x; 1.0517x over previous
#include <cuda_runtime.h>
#include <cuda_bf16.h>
#include <cstdint>

// Problem constants
#define BB 32
#define TT 1024
#define DD 128
#define HH 4
#define DHH 32
#define MROWS (BB*TT)   // 32768

// Scratch (device globals — no allocation allowed)
__device__ __align__(16) uint32_t g_Asp[MROWS * DD];    // attn out pre-split
__device__ __align__(16) uint32_t g_Ws[384 * 128];      // W^T split
__device__ __align__(16) uint32_t g_WOs[128 * 128];     // Wout^T split
__device__ __align__(16) uint32_t g_Qsp[MROWS * HH * 32];        // Q split (scaled)
__device__ __align__(16) uint32_t g_Ksp[BB * HH * TT * 32];      // K split rows
__device__ __align__(16) uint32_t g_Vth[BB * HH * 32 * (TT/2)];  // V^T hi
__device__ __align__(16) uint32_t g_Vtl[BB * HH * 32 * (TT/2)];  // V^T lo

// ---------------------------------------------------------------------------
// helpers
// ---------------------------------------------------------------------------
__device__ __forceinline__ uint32_t smem_u32(const void* p) {
    uint32_t a;
    asm("{ .reg .u64 t; cvta.to.shared.u64 t, %1; cvt.u32.u64 %0, t; }"
        : "=r"(a) : "l"(p));
    return a;
}

__device__ __forceinline__ uint32_t split_pack(float x) {
    __nv_bfloat16 h = __float2bfloat16(x);
    float r = x - __bfloat162float(h);
    __nv_bfloat16 l = __float2bfloat16(r);
    return (uint32_t)__bfloat16_as_ushort(h) | ((uint32_t)__bfloat16_as_ushort(l) << 16);
}

__device__ __forceinline__ uint32_t pack_bf16x2(float x, float y) {
    uint32_t d;
    asm("cvt.rn.bf16x2.f32 %0, %1, %2;" : "=r"(d) : "f"(y), "f"(x));
    return d;
}

__device__ __forceinline__ void pair_split(float x, float y,
                                           uint32_t& hi, uint32_t& lo) {
    hi = pack_bf16x2(x, y);
    float hx = __uint_as_float(hi << 16);
    float hy = __uint_as_float(hi & 0xffff0000u);
    lo = pack_bf16x2(x - hx, y - hy);
}

__device__ __forceinline__ float ex2f(float x) {
    float r;
    asm("ex2.approx.ftz.f32 %0, %1;" : "=f"(r) : "f"(x));
    return r;
}

#define LDSM_X4(r0, r1, r2, r3, addr) \
    asm volatile("ldmatrix.sync.aligned.m8n8.x4.shared.b16 {%0,%1,%2,%3}, [%4];" \
                 : "=r"(r0), "=r"(r1), "=r"(r2), "=r"(r3) : "r"(addr))

#define LDSM_X2(r0, r1, addr) \
    asm volatile("ldmatrix.sync.aligned.m8n8.x2.shared.b16 {%0,%1}, [%2];" \
                 : "=r"(r0), "=r"(r1) : "r"(addr))

#define MMA_16816(c, a, b) \
    asm volatile("mma.sync.aligned.m16n8k16.row.col.f32.bf16.bf16.f32 " \
                 "{%0,%1,%2,%3}, {%4,%5,%6,%7}, {%8,%9}, {%0,%1,%2,%3};" \
                 : "+f"((c)[0]), "+f"((c)[1]), "+f"((c)[2]), "+f"((c)[3]) \
                 : "r"((a)[0]), "r"((a)[1]), "r"((a)[2]), "r"((a)[3]), \
                   "r"((b)[0]), "r"((b)[1]))

#define CP_ASYNC16(dst, src) \
    asm volatile("cp.async.cg.shared.global [%0], [%1], 16;" :: "r"(dst), "l"(src))
#define CP_COMMIT() asm volatile("cp.async.commit_group;" ::: "memory")
#define CP_WAIT(n)  asm volatile("cp.async.wait_group %0;" :: "n"(n) : "memory")

// ---------------------------------------------------------------------------
// Prepass (weights only): transpose W / W_output and split fp32 -> bf16 pairs.
// ---------------------------------------------------------------------------
__global__ void wsplit_kernel(const float* __restrict__ W,
                              const float* __restrict__ Wo,
                              uint32_t* __restrict__ Ws,
                              uint32_t* __restrict__ WOs) {
    int n = blockIdx.x;
    int k = threadIdx.x;   // 0..127
    if (n < 384) {
        Ws[n * 128 + k] = split_pack(W[k * 384 + n]);
    } else {
        int nn = n - 384;
        WOs[nn * 128 + k] = split_pack(Wo[k * 128 + nn]);
    }
}

// ---------------------------------------------------------------------------
// QKV HMMA GEMM: fp32 x split in-kernel (A read exactly once per CTA),
// pre-split W (B read as uint4). M-tile 128; fused Q/K/V epilogues.
// ---------------------------------------------------------------------------
__global__ __launch_bounds__(256) void gemm_qkv(
    const float* __restrict__ X, const uint32_t* __restrict__ Bg,
    uint32_t* __restrict__ Qsp, uint32_t* __restrict__ Ksp,
    uint32_t* __restrict__ Vth, uint32_t* __restrict__ Vtl) {
    __shared__ uint32_t As_s[128 * 36];
    __shared__ uint32_t Bs_s[128 * 36];

    const int tid = threadIdx.x;
    const int wid = tid >> 5;
    const int lane = tid & 31;
    const int wm = wid >> 2;
    const int wn = wid & 3;
    const int m0 = blockIdx.x * 128;
    const int y = blockIdx.y;
    const int n0 = y * 128;

    const uint32_t sa = smem_u32(As_s);
    const uint32_t sb = smem_u32(Bs_s);

    float acc[4][4][4];
#pragma unroll
    for (int i = 0; i < 4; i++)
#pragma unroll
        for (int j = 0; j < 4; j++)
#pragma unroll
            for (int q = 0; q < 4; q++) acc[i][j][q] = 0.f;

    const int a_row = lane & 15;
    const int a_koff = (lane >> 4) * 4;
    const int b_row = lane & 7;
    const int b_koff = ((lane >> 3) & 1) * 4;

    for (int ch = 0; ch < 4; ch++) {
        const int kc = ch * 32;
        // A chunk: 128 rows x 32 fp32 of x -> split in-kernel (x read once)
#pragma unroll
        for (int r = 0; r < 4; r++) {
            int idx = tid + r * 256;
            int row = idx >> 3, c4 = idx & 7;
            float4 v = *(const float4*)&X[(size_t)(m0 + row) * 128 + kc + c4 * 4];
            uint32_t* d = &As_s[row * 36 + c4 * 4];
            d[0] = split_pack(v.x); d[1] = split_pack(v.y);
            d[2] = split_pack(v.z); d[3] = split_pack(v.w);
        }
        // B chunk: pre-split weights, uint4 loads
#pragma unroll
        for (int r = 0; r < 4; r++) {
            int idx = tid + r * 256;
            int row = idx >> 3, c16 = idx & 7;
            uint4 v = *(const uint4*)&Bg[(size_t)(n0 + row) * 128 + kc + c16 * 4];
            uint32_t* d = &Bs_s[row * 36 + c16 * 4];
            d[0] = v.x; d[1] = v.y; d[2] = v.z; d[3] = v.w;
        }
        __syncthreads();

#pragma unroll
        for (int s = 0; s < 4; s++) {
            uint32_t af[4][4];
#pragma unroll
            for (int tm = 0; tm < 4; tm++) {
                uint32_t addr = sa + (uint32_t)(((wm * 64 + tm * 16 + a_row) * 36 +
                                                 s * 8 + a_koff) * 4);
                LDSM_X4(af[tm][0], af[tm][1], af[tm][2], af[tm][3], addr);
            }
            uint32_t bf[4][2];
#pragma unroll
            for (int tn = 0; tn < 4; tn++) {
                uint32_t addr = sb + (uint32_t)(((wn * 32 + tn * 8 + b_row) * 36 +
                                                 s * 8 + b_koff) * 4);
                LDSM_X2(bf[tn][0], bf[tn][1], addr);
            }
#pragma unroll
            for (int tm = 0; tm < 4; tm++)
#pragma unroll
                for (int tn = 0; tn < 4; tn++)
                    MMA_16816(acc[tm][tn], af[tm], bf[tn]);
        }
        __syncthreads();
    }

    const int er = lane >> 2;
    const int ec = (lane & 3) * 2;
    const float qscale = 0.17677669529663687f * 1.4426950408889634f;

    if (y == 2) {
        float* sv = (float*)As_s;   // stride 34 (even), 128*34*4 = 17.4 KB
        const int b = m0 >> 10;
        const int jb0 = m0 & 1023;
#pragma unroll
        for (int h = 0; h < 4; h++) {
            if (h) __syncthreads();
            if (wn == h) {
#pragma unroll
                for (int tm = 0; tm < 4; tm++) {
#pragma unroll
                    for (int tn = 0; tn < 4; tn++) {
                        int rl = wm * 64 + tm * 16 + er;
                        int cl = tn * 8 + ec;
                        *(float2*)&sv[rl * 34 + cl] =
                            make_float2(acc[tm][tn][0], acc[tm][tn][1]);
                        *(float2*)&sv[(rl + 8) * 34 + cl] =
                            make_float2(acc[tm][tn][2], acc[tm][tn][3]);
                    }
                }
            }
            __syncthreads();
            const int bh = b * 4 + h;
#pragma unroll
            for (int r = 0; r < 8; r++) {
                int idx = tid + r * 256;
                int d = idx >> 6, jp = idx & 63;
                uint32_t hi, lo;
                pair_split(sv[(jp * 2) * 34 + d], sv[(jp * 2 + 1) * 34 + d], hi, lo);
                size_t o = (size_t)(bh * 32 + d) * (TT / 2) + (jb0 >> 1) + jp;
                Vth[o] = hi;
                Vtl[o] = lo;
            }
        }
    } else {
        const float sc = (y == 0) ? qscale : 1.f;
#pragma unroll
        for (int tm = 0; tm < 4; tm++) {
#pragma unroll
            for (int tn = 0; tn < 4; tn++) {
                int row = m0 + wm * 64 + tm * 16 + er;
                int col = wn * 32 + tn * 8 + ec;
                int head = col >> 5;
                int dp = (col & 31) >> 1;
                uint32_t hi0, lo0, hi1, lo1;
                pair_split(acc[tm][tn][0] * sc, acc[tm][tn][1] * sc, hi0, lo0);
                pair_split(acc[tm][tn][2] * sc, acc[tm][tn][3] * sc, hi1, lo1);
                if (y == 0) {
                    uint32_t* d0 = &Qsp[((size_t)row * 4 + head) * 32];
                    uint32_t* d1 = &Qsp[((size_t)(row + 8) * 4 + head) * 32];
                    d0[dp] = hi0; d0[16 + dp] = lo0;
                    d1[dp] = hi1; d1[16 + dp] = lo1;
                } else {
                    int bb = row >> 10;
                    int t0 = row & 1023;
                    uint32_t* d0 = &Ksp[(((size_t)bb * 4 + head) * 1024 + t0) * 32];
                    uint32_t* d1 = d0 + 8 * 32;
                    d0[dp] = hi0; d0[16 + dp] = lo0;
                    d1[dp] = hi1; d1[16 + dp] = lo1;
                }
            }
        }
    }
}

// ---------------------------------------------------------------------------
// Fused output projection (pre-split A + pre-split W_output) +
// residual(acc-init) + LayerNorm.  (R15 winner, unchanged.)
// ---------------------------------------------------------------------------
__global__ __launch_bounds__(256) void gemm_out_ln(
    const uint32_t* __restrict__ Asp, const uint32_t* __restrict__ Bg,
    const float* __restrict__ x, const float* __restrict__ gamma,
    const float* __restrict__ beta, float* __restrict__ out) {
    __shared__ uint32_t As_s[128 * 36];
    __shared__ uint32_t Bs_s[128 * 36];

    const int tid = threadIdx.x;
    const int wid = tid >> 5;
    const int lane = tid & 31;
    const int wm = wid >> 2;
    const int wn = wid & 3;
    const int m0 = blockIdx.x * 128;

    const uint32_t sa = smem_u32(As_s);
    const uint32_t sb = smem_u32(Bs_s);

    const int er = lane >> 2;
    const int ec = (lane & 3) * 2;

    float acc[4][4][4];
#pragma unroll
    for (int tm = 0; tm < 4; tm++) {
#pragma unroll
        for (int tn = 0; tn < 4; tn++) {
            int row = m0 + wm * 64 + tm * 16 + er;
            int col = wn * 32 + tn * 8 + ec;
            float2 x0 = *(const float2*)&x[(size_t)row * 128 + col];
            float2 x1 = *(const float2*)&x[(size_t)(row + 8) * 128 + col];
            acc[tm][tn][0] = x0.x; acc[tm][tn][1] = x0.y;
            acc[tm][tn][2] = x1.x; acc[tm][tn][3] = x1.y;
        }
    }

    const int a_row = lane & 15;
    const int a_koff = (lane >> 4) * 4;
    const int b_row = lane & 7;
    const int b_koff = ((lane >> 3) & 1) * 4;

    for (int ch = 0; ch < 4; ch++) {
        const int kc = ch * 32;
#pragma unroll
        for (int r = 0; r < 4; r++) {
            int idx = tid + r * 256;
            int row = idx >> 3, c4 = idx & 7;
            uint4 v = *(const uint4*)&Asp[(size_t)(m0 + row) * 128 + kc + c4 * 4];
            uint32_t* d = &As_s[row * 36 + c4 * 4];
            d[0] = v.x; d[1] = v.y; d[2] = v.z; d[3] = v.w;
        }
#pragma unroll
        for (int r = 0; r < 4; r++) {
            int idx = tid + r * 256;
            int row = idx >> 3, c16 = idx & 7;
            uint4 v = *(const uint4*)&Bg[(size_t)row * 128 + kc + c16 * 4];
            uint32_t* d = &Bs_s[row * 36 + c16 * 4];
            d[0] = v.x; d[1] = v.y; d[2] = v.z; d[3] = v.w;
        }
        __syncthreads();

#pragma unroll
        for (int s = 0; s < 4; s++) {
            uint32_t af[4][4];
#pragma unroll
            for (int tm = 0; tm < 4; tm++) {
                uint32_t addr = sa + (uint32_t)(((wm * 64 + tm * 16 + a_row) * 36 +
                                                 s * 8 + a_koff) * 4);
                LDSM_X4(af[tm][0], af[tm][1], af[tm][2], af[tm][3], addr);
            }
            uint32_t bf[4][2];
#pragma unroll
            for (int tn = 0; tn < 4; tn++) {
                uint32_t addr = sb + (uint32_t)(((wn * 32 + tn * 8 + b_row) * 36 +
                                                 s * 8 + b_koff) * 4);
                LDSM_X2(bf[tn][0], bf[tn][1], addr);
            }
#pragma unroll
            for (int tm = 0; tm < 4; tm++)
#pragma unroll
                for (int tn = 0; tn < 4; tn++)
                    MMA_16816(acc[tm][tn], af[tm], bf[tn]);
        }
        __syncthreads();
    }

    float2* red = (float2*)As_s;
#pragma unroll
    for (int tm = 0; tm < 4; tm++) {
        float s0 = 0.f, q0 = 0.f, s1 = 0.f, q1 = 0.f;
#pragma unroll
        for (int tn = 0; tn < 4; tn++) {
            s0 += acc[tm][tn][0] + acc[tm][tn][1];
            q0 += acc[tm][tn][0] * acc[tm][tn][0] + acc[tm][tn][1] * acc[tm][tn][1];
            s1 += acc[tm][tn][2] + acc[tm][tn][3];
            q1 += acc[tm][tn][2] * acc[tm][tn][2] + acc[tm][tn][3] * acc[tm][tn][3];
        }
#pragma unroll
        for (int off = 1; off < 4; off <<= 1) {
            s0 += __shfl_xor_sync(0xffffffffu, s0, off);
            q0 += __shfl_xor_sync(0xffffffffu, q0, off);
            s1 += __shfl_xor_sync(0xffffffffu, s1, off);
            q1 += __shfl_xor_sync(0xffffffffu, q1, off);
        }
        if ((lane & 3) == 0) {
            int rl = wm * 64 + tm * 16 + er;
            red[wn * 128 + rl] = make_float2(s0, q0);
            red[wn * 128 + rl + 8] = make_float2(s1, q1);
        }
    }
    __syncthreads();

    float2 gm[4], bt[4];
#pragma unroll
    for (int tn = 0; tn < 4; tn++) {
        int col = wn * 32 + tn * 8 + ec;
        gm[tn] = *(const float2*)&gamma[col];
        bt[tn] = *(const float2*)&beta[col];
    }

#pragma unroll
    for (int tm = 0; tm < 4; tm++) {
        int rl = wm * 64 + tm * 16 + er;
        float s0 = 0.f, q0 = 0.f, s1 = 0.f, q1 = 0.f;
#pragma unroll
        for (int w = 0; w < 4; w++) {
            float2 p0 = red[w * 128 + rl];
            float2 p1 = red[w * 128 + rl + 8];
            s0 += p0.x; q0 += p0.y;
            s1 += p1.x; q1 += p1.y;
        }
        float mean0 = s0 * (1.f / 128.f);
        float var0 = q0 * (1.f / 128.f) - mean0 * mean0;
        float rstd0 = rsqrtf(var0 + 1e-9f);
        float mean1 = s1 * (1.f / 128.f);
        float var1 = q1 * (1.f / 128.f) - mean1 * mean1;
        float rstd1 = rsqrtf(var1 + 1e-9f);

        int row = m0 + rl;
#pragma unroll
        for (int tn = 0; tn < 4; tn++) {
            int col = wn * 32 + tn * 8 + ec;
            float2 o0 = make_float2(
                (acc[tm][tn][0] - mean0) * rstd0 * gm[tn].x + bt[tn].x,
                (acc[tm][tn][1] - mean0) * rstd0 * gm[tn].y + bt[tn].y);
            float2 o1 = make_float2(
                (acc[tm][tn][2] - mean1) * rstd1 * gm[tn].x + bt[tn].x,
                (acc[tm][tn][3] - mean1) * rstd1 * gm[tn].y + bt[tn].y);
            *(float2*)&out[(size_t)row * 128 + col] = o0;
            *(float2*)&out[(size_t)(row + 8) * 128 + col] = o1;
        }
    }
}

// ---------------------------------------------------------------------------
// HMMA flash attention, no-max softmax (frozen R15 winner).
// ---------------------------------------------------------------------------
__global__ __launch_bounds__(256, 3) void attn_hmma(
    const uint32_t* __restrict__ Qsp, const int* __restrict__ keys_length,
    const uint32_t* __restrict__ Ksp, const uint32_t* __restrict__ Vth,
    const uint32_t* __restrict__ Vtl, uint32_t* __restrict__ outsp) {
    __shared__ __align__(16) uint32_t S[9216];

    const int bid = blockIdx.x;
    const int q0 = (7 - (bid >> 7)) * 128;
    const int bh = bid & 127;
    const int h = bh & 3;
    const int b = bh >> 2;
    const int tid = threadIdx.x;
    const int wid = tid >> 5;
    const int lane = tid & 31;
    const uint32_t sS = smem_u32(S);

    const int L = keys_length[b];
    const int kend = min(q0 + 128, L);
    const int ntiles = (kend + 63) >> 6;

    const uint32_t* kbase = Ksp + (size_t)(bh * TT) * 32;
    const uint32_t* vhbase = Vth + (size_t)(bh * 32) * (TT / 2);
    const uint32_t* vlbase = Vtl + (size_t)(bh * 32) * (TT / 2);

    {
        const uint32_t sk = sS;
        const uint32_t* kt = kbase;
#pragma unroll
        for (int r = 0; r < 2; r++) {
            int idx = tid + r * 256;
            int row = idx >> 3, c4 = idx & 7;
            CP_ASYNC16(sk + (uint32_t)((row * 36 + c4 * 4) * 4), kt + row * 32 + c4 * 4);
        }
        {
            int d = tid >> 3, c4 = tid & 7;
            CP_ASYNC16(sk + (uint32_t)((2304 + d * 36 + c4 * 4) * 4),
                       vhbase + (size_t)d * (TT / 2) + c4 * 4);
            CP_ASYNC16(sk + (uint32_t)((3456 + d * 36 + c4 * 4) * 4),
                       vlbase + (size_t)d * (TT / 2) + c4 * 4);
        }
#pragma unroll
        for (int r = 0; r < 4; r++) {
            int idx = tid + r * 256;
            int row = idx >> 3, c4 = idx & 7;
            CP_ASYNC16(sS + (uint32_t)((4608 + row * 36 + c4 * 4) * 4),
                       Qsp + ((size_t)(b * TT + q0 + row) * 4 + h) * 32 + c4 * 4);
        }
        CP_COMMIT();
    }

    CP_WAIT(0);
    __syncthreads();

    const int a_row = lane & 15;
    const int a_koff = (lane >> 4) * 4;
    uint32_t aH[2][4], aL[2][4];
#pragma unroll
    for (int ks = 0; ks < 2; ks++) {
        uint32_t addr = sS + (uint32_t)((4608 + (wid * 16 + a_row) * 36 + ks * 8 + a_koff) * 4);
        LDSM_X4(aH[ks][0], aH[ks][1], aH[ks][2], aH[ks][3], addr);
        LDSM_X4(aL[ks][0], aL[ks][1], aL[ks][2], aL[ks][3], addr + 64);
    }
    __syncthreads();

    float o[4][4];
#pragma unroll
    for (int nt = 0; nt < 4; nt++)
#pragma unroll
        for (int c = 0; c < 4; c++) o[nt][c] = 0.f;
    float l0 = 0.f, l1 = 0.f;

    const int r0 = q0 + wid * 16 + (lane >> 2);
    const int r1 = r0 + 8;
    const int rmax = q0 + wid * 16 + 15;
    const int b_row = lane & 7;
    const int b_k4 = (lane >> 3) * 4;

    for (int t = 0; t < ntiles; t++) {
        if (t + 1 < ntiles) {
            const uint32_t sk = sS + (uint32_t)(((t + 1) & 1) * 4608 * 4);
            const uint32_t* kt = kbase + (size_t)(t + 1) * 64 * 32;
#pragma unroll
            for (int r = 0; r < 2; r++) {
                int idx = tid + r * 256;
                int row = idx >> 3, c4 = idx & 7;
                CP_ASYNC16(sk + (uint32_t)((row * 36 + c4 * 4) * 4), kt + row * 32 + c4 * 4);
            }
            {
                int d = tid >> 3, c4 = tid & 7;
                CP_ASYNC16(sk + (uint32_t)((2304 + d * 36 + c4 * 4) * 4),
                           vhbase + (size_t)d * (TT / 2) + (t + 1) * 32 + c4 * 4);
                CP_ASYNC16(sk + (uint32_t)((3456 + d * 36 + c4 * 4) * 4),
                           vlbase + (size_t)d * (TT / 2) + (t + 1) * 32 + c4 * 4);
            }
            CP_COMMIT();
            CP_WAIT(1);
        } else {
            CP_WAIT(0);
        }
        __syncthreads();

        const int j0 = t * 64;
        if (j0 <= rmax) {
            const uint32_t skb = sS + (uint32_t)((t & 1) * 4608 * 4);

            float s[8][4];
#pragma unroll
            for (int tt = 0; tt < 8; tt++)
#pragma unroll
                for (int c = 0; c < 4; c++) s[tt][c] = 0.f;

#pragma unroll
            for (int tt = 0; tt < 8; tt++) {
                uint32_t krow = skb + (uint32_t)(((tt * 8 + b_row) * 36 + b_k4) * 4);
                uint32_t bh0[2], bh1[2], bl0[2], bl1[2];
                LDSM_X4(bh0[0], bh0[1], bh1[0], bh1[1], krow);
                LDSM_X4(bl0[0], bl0[1], bl1[0], bl1[1], krow + 64);
                MMA_16816(s[tt], aH[0], bh0);
                MMA_16816(s[tt], aH[1], bh1);
                MMA_16816(s[tt], aL[0], bh0);
                MMA_16816(s[tt], aL[1], bh1);
                MMA_16816(s[tt], aH[0], bl0);
                MMA_16816(s[tt], aH[1], bl1);
            }

            const bool needMask = (j0 + 64 > L) || (j0 + 64 > q0 + wid * 16 + 1);
            if (needMask) {
#pragma unroll
                for (int tt = 0; tt < 8; tt++) {
#pragma unroll
                    for (int c = 0; c < 2; c++) {
                        int j = j0 + tt * 8 + (lane & 3) * 2 + c;
                        if (j > r0 || j >= L) s[tt][c] = -1e30f;
                        if (j > r1 || j >= L) s[tt][2 + c] = -1e30f;
                    }
                }
            }

            // ---- softmax numerator, no max shift ----
#pragma unroll
            for (int tt = 0; tt < 8; tt++) {
                s[tt][0] = ex2f(s[tt][0]);
                s[tt][1] = ex2f(s[tt][1]);
                s[tt][2] = ex2f(s[tt][2]);
                s[tt][3] = ex2f(s[tt][3]);
                l0 += s[tt][0] + s[tt][1];
                l1 += s[tt][2] + s[tt][3];
            }

            // ---- PV: stream P per ks-pair ----
            const uint32_t svhb = skb + 2304 * 4;
            const uint32_t svlb = skb + 3456 * 4;
#pragma unroll
            for (int ksp = 0; ksp < 2; ksp++) {
                uint32_t ph2[2][4], pl2[2][4];
#pragma unroll
                for (int k2 = 0; k2 < 2; k2++) {
                    const int t0 = 4 * ksp + 2 * k2, t1 = t0 + 1;
                    float v[8] = {s[t0][0], s[t0][1], s[t0][2], s[t0][3],
                                  s[t1][0], s[t1][1], s[t1][2], s[t1][3]};
#pragma unroll
                    for (int g = 0; g < 4; g++) {
                        pair_split(v[g * 2], v[g * 2 + 1], ph2[k2][g], pl2[k2][g]);
                    }
                }
#pragma unroll
                for (int nt = 0; nt < 4; nt++) {
                    uint32_t voff = (uint32_t)(((nt * 8 + b_row) * 36 + b_k4) * 4) +
                                    (uint32_t)(ksp * 64);
                    uint32_t bvh[2][2], bvl[2][2];
                    LDSM_X4(bvh[0][0], bvh[0][1], bvh[1][0], bvh[1][1], svhb + voff);
                    LDSM_X4(bvl[0][0], bvl[0][1], bvl[1][0], bvl[1][1], svlb + voff);
#pragma unroll
                    for (int k2 = 0; k2 < 2; k2++) {
                        MMA_16816(o[nt], ph2[k2], bvh[k2]);
                        MMA_16816(o[nt], pl2[k2], bvh[k2]);
                        MMA_16816(o[nt], ph2[k2], bvl[k2]);
                    }
                }
            }
        }
        __syncthreads();
    }

    l0 += __shfl_xor_sync(0xffffffffu, l0, 1);
    l0 += __shfl_xor_sync(0xffffffffu, l0, 2);
    l1 += __shfl_xor_sync(0xffffffffu, l1, 1);
    l1 += __shfl_xor_sync(0xffffffffu, l1, 2);
    const float inv0 = 1.f / l0, inv1 = 1.f / l1;
#pragma unroll
    for (int nt = 0; nt < 4; nt++) {
        int d = h * 32 + nt * 8 + (lane & 3) * 2;
        *(uint2*)&outsp[((size_t)(b * TT + r0)) * DD + d] =
            make_uint2(split_pack(o[nt][0] * inv0), split_pack(o[nt][1] * inv0));
        *(uint2*)&outsp[((size_t)(b * TT + r1)) * DD + d] =
            make_uint2(split_pack(o[nt][2] * inv1), split_pack(o[nt][3] * inv1));
    }
}

// ---------------------------------------------------------------------------
extern "C" void kernel_launch(void* const* d_in, const int* in_sizes, int n_in,
                              void* d_out, int out_size) {
    const float* x           = (const float*)d_in[0];
    const int*   keys_length = (const int*)d_in[1];
    const float* W           = (const float*)d_in[2];
    const float* W_output    = (const float*)d_in[3];
    const float* gamma       = (const float*)d_in[4];
    const float* beta        = (const float*)d_in[5];
    float* out = (float*)d_out;

    uint32_t *asp_p, *ws_p, *wos_p, *qsp_p, *ksp_p, *vth_p, *vtl_p;
    cudaGetSymbolAddress((void**)&asp_p, g_Asp);
    cudaGetSymbolAddress((void**)&ws_p,  g_Ws);
    cudaGetSymbolAddress((void**)&wos_p, g_WOs);
    cudaGetSymbolAddress((void**)&qsp_p, g_Qsp);
    cudaGetSymbolAddress((void**)&ksp_p, g_Ksp);
    cudaGetSymbolAddress((void**)&vth_p, g_Vth);
    cudaGetSymbolAddress((void**)&vtl_p, g_Vtl);

    // 0) Weight transpose + split (weights only, tiny)
    wsplit_kernel<<<512, 128>>>(W, W_output, ws_p, wos_p);

    // 1) QKV projection: fp32 x split in-kernel, pre-split W
    gemm_qkv<<<dim3(MROWS / 128, 3), 256>>>(x, ws_p, qsp_p, ksp_p,
                                            vth_p, vtl_p);

    // 2) Flash attention (HMMA, no-max softmax); output pre-split
    attn_hmma<<<1024, 256>>>(qsp_p, keys_length, ksp_p, vth_p, vtl_p, asp_p);

    // 3) Output projection (pre-split W_output) + residual + LN
    gemm_out_ln<<<MROWS / 128, 256>>>(asp_p, wos_p, x, gamma, beta, out);
}